// round 2
// baseline (speedup 1.0000x reference)
#include <cuda_runtime.h>

// Device scratch (no allocations allowed).
// g_T[i]: affine transform buffer, 64 rows x 72 cols; P in cols 0..63, s in col 64.
__device__ float g_T[4][64 * 72];
// Folded conv weights: 64 rows x 180 cols; cols 0..167 = A*W1pad (kx padded to 8),
// col 168 = beff = A*b1 + s200.
__device__ float g_W1f[64 * 180];

#define W1F_LD 180

// ---------------------------------------------------------------------------
// step: C = A ∘ B  (affine compose).  C.P = A.P * B.P ; C.s = A.P*B.s + A.s
// ai/bi = -1 means "read (W2, b2) from globals", else index into g_T.
// grid 9 blocks x 512 threads; block b computes columns [b*8, b*8+8) of [P|s].
// ---------------------------------------------------------------------------
__global__ void __launch_bounds__(512, 1)
step_k(const float* __restrict__ W2, const float* __restrict__ b2,
       int ai, int bi, int ci)
{
    const float* A;  int lda; const float* As; int sas;
    if (ai < 0) { A = W2;      lda = 64; As = b2;           sas = 1;  }
    else        { A = g_T[ai]; lda = 72; As = g_T[ai] + 64; sas = 72; }
    const float* B;  int ldb; const float* Bs; int sbs;
    if (bi < 0) { B = W2;      ldb = 64; Bs = b2;           sbs = 1;  }
    else        { B = g_T[bi]; ldb = 72; Bs = g_T[bi] + 64; sbs = 72; }
    float* C = g_T[ci];

    __shared__ float Asm[64 * 64];
    __shared__ float Bt[64][9];   // 8 cols + pad

    const int t  = threadIdx.x;
    const int j0 = blockIdx.x * 8;

    for (int i = t; i < 4096; i += 512)
        Asm[i] = A[(i >> 6) * lda + (i & 63)];
    {
        const int k = t >> 3, jj = t & 7, j = j0 + jj;
        float v = 0.0f;
        if (j < 64)       v = B[k * ldb + j];
        else if (j == 64) v = Bs[k * sbs];
        Bt[k][jj] = v;
    }
    __syncthreads();

    const int r = t >> 3, jj = t & 7, j = j0 + jj;
    float c = 0.0f;
#pragma unroll
    for (int k = 0; k < 64; ++k)
        c = fmaf(Asm[r * 64 + k], Bt[k][jj], c);
    if (j == 64) c += As[r * sas];
    if (j <= 64) C[r * 72 + j] = c;
}

// ---------------------------------------------------------------------------
// fold: g_W1f = P200 * [W1pad | b1], plus s200 added to the b1 column.
// grid 22 blocks x 512 threads; block b computes columns [b*8, b*8+8).
// ---------------------------------------------------------------------------
__global__ void __launch_bounds__(512, 1)
fold_k(const float* __restrict__ W1, const float* __restrict__ b1)
{
    __shared__ float Asm[64 * 64];
    __shared__ float Bt[64][9];

    const int t  = threadIdx.x;
    const int j0 = blockIdx.x * 8;

    for (int i = t; i < 4096; i += 512)
        Asm[i] = g_T[0][(i >> 6) * 72 + (i & 63)];
    {
        const int m = t >> 3, jj = t & 7, j = j0 + jj;
        float v = 0.0f;
        if (j < 168) {
            int ii = j / 56, rr = j % 56, ky = rr / 8, kx = rr % 8;
            if (kx < 7) v = W1[m * 147 + ii * 49 + ky * 7 + kx];
        } else if (j == 168) {
            v = b1[m];
        }
        Bt[m][jj] = v;
    }
    __syncthreads();

    const int r = t >> 3, jj = t & 7, j = j0 + jj;
    float c = 0.0f;
#pragma unroll
    for (int k = 0; k < 64; ++k)
        c = fmaf(Asm[r * 64 + k], Bt[k][jj], c);
    if (j == 168) c += g_T[0][r * 72 + 64];   // + s200
    if (j <= 168) g_W1f[r * W1F_LD + j] = c;
}

// ---------------------------------------------------------------------------
// conv: out = conv7x7(x, W1f) + beff, using folded weights from g_W1f.
// 128 blocks x 256 threads. Block b handles output rows (b*2, b*2+1).
// Thread: xq = t&7 -> 8 px (x0=xq*8); op = t>>3 -> 2 out-ch (o0=op*2); both rows.
// ---------------------------------------------------------------------------
#define CONV_SMEM ((64 * W1F_LD + 2 * 3 * 7 * 72) * 4)

__global__ void __launch_bounds__(256, 1)
conv_k(const float* __restrict__ x, float* __restrict__ out)
{
    extern __shared__ float sm[];
    float* W1s = sm;                 // 64 x 180
    float* xs  = sm + 64 * W1F_LD;   // 2 x 3 x 7 x 72

    const int t   = threadIdx.x;
    const int bid = blockIdx.x;
    const int r0  = bid * 2;
    const int bb0 = r0 >> 6,       y0 = r0 & 63;
    const int bb1 = (r0 + 1) >> 6, y1 = (r0 + 1) & 63;

    for (int i = t; i < 64 * W1F_LD; i += 256)
        W1s[i] = g_W1f[i];
    for (int i = t; i < 3024; i += 256) {
        int row = i / 1512, rem = i % 1512;
        int ii = rem / 504, rem2 = rem % 504;
        int ky = rem2 / 72, xx = rem2 % 72;
        int bb = row ? bb1 : bb0;
        int yy = (row ? y1 : y0) + ky;
        xs[i] = (xx < 70) ? x[((bb * 3 + ii) * 70 + yy) * 70 + xx] : 0.0f;
    }
    __syncthreads();

    const int xq = t & 7, op = t >> 3;
    const int x0 = xq * 8, o0 = op * 2;

    float acc[2][2][8];
#pragma unroll
    for (int oo = 0; oo < 2; ++oo) {
        float bv = W1s[(o0 + oo) * W1F_LD + 168];
#pragma unroll
        for (int r = 0; r < 2; ++r)
#pragma unroll
            for (int xi = 0; xi < 8; ++xi) acc[r][oo][xi] = bv;
    }

#pragma unroll 1
    for (int ii = 0; ii < 3; ++ii) {
#pragma unroll 1
        for (int ky = 0; ky < 7; ++ky) {
            float xw[2][16];
#pragma unroll
            for (int r = 0; r < 2; ++r) {
                const float* p = xs + (r * 21 + ii * 7 + ky) * 72 + x0;
                float4 u0 = *(const float4*)(p);
                float4 u1 = *(const float4*)(p + 4);
                float4 u2 = *(const float4*)(p + 8);
                float4 u3 = *(const float4*)(p + 12);
                xw[r][0]  = u0.x; xw[r][1]  = u0.y; xw[r][2]  = u0.z; xw[r][3]  = u0.w;
                xw[r][4]  = u1.x; xw[r][5]  = u1.y; xw[r][6]  = u1.z; xw[r][7]  = u1.w;
                xw[r][8]  = u2.x; xw[r][9]  = u2.y; xw[r][10] = u2.z; xw[r][11] = u2.w;
                xw[r][12] = u3.x; xw[r][13] = u3.y; xw[r][14] = u3.z; xw[r][15] = u3.w;
            }
            float wv[2][8];
#pragma unroll
            for (int oo = 0; oo < 2; ++oo) {
                const float* p = W1s + (o0 + oo) * W1F_LD + ii * 56 + ky * 8;
                float4 w0 = *(const float4*)(p);
                float4 w1 = *(const float4*)(p + 4);
                wv[oo][0] = w0.x; wv[oo][1] = w0.y; wv[oo][2] = w0.z; wv[oo][3] = w0.w;
                wv[oo][4] = w1.x; wv[oo][5] = w1.y; wv[oo][6] = w1.z; wv[oo][7] = w1.w;
            }
#pragma unroll
            for (int kx = 0; kx < 7; ++kx)
#pragma unroll
                for (int r = 0; r < 2; ++r)
#pragma unroll
                    for (int oo = 0; oo < 2; ++oo)
#pragma unroll
                        for (int xi = 0; xi < 8; ++xi)
                            acc[r][oo][xi] = fmaf(wv[oo][kx], xw[r][kx + xi], acc[r][oo][xi]);
        }
    }

#pragma unroll
    for (int r = 0; r < 2; ++r) {
        const int bb = r ? bb1 : bb0;
        const int yy = r ? y1 : y0;
#pragma unroll
        for (int oo = 0; oo < 2; ++oo) {
            float* po = out + ((bb * 64 + (o0 + oo)) * 64 + yy) * 64 + x0;
            *(float4*)(po)     = make_float4(acc[r][oo][0], acc[r][oo][1],
                                             acc[r][oo][2], acc[r][oo][3]);
            *(float4*)(po + 4) = make_float4(acc[r][oo][4], acc[r][oo][5],
                                             acc[r][oo][6], acc[r][oo][7]);
        }
    }
}

extern "C" void kernel_launch(void* const* d_in, const int* in_sizes, int n_in,
                              void* d_out, int out_size)
{
    (void)in_sizes; (void)n_in; (void)out_size;
    const float* x  = (const float*)d_in[0];
    const float* W1 = (const float*)d_in[1];
    const float* b1 = (const float*)d_in[2];
    const float* W2 = (const float*)d_in[3];
    const float* b2 = (const float*)d_in[4];
    float* out = (float*)d_out;

    cudaFuncSetAttribute(conv_k, cudaFuncAttributeMaxDynamicSharedMemorySize,
                         CONV_SMEM);

    // Addition chain for 200: 2,4,8,16,32,64,128,192(=128+64),200(=192+8)
    step_k<<<9, 512>>>(W2, b2, -1, -1, 0);   // T2   -> g_T[0]
    step_k<<<9, 512>>>(W2, b2,  0,  0, 1);   // T4   -> g_T[1]
    step_k<<<9, 512>>>(W2, b2,  1,  1, 2);   // T8   -> g_T[2]  (kept)
    step_k<<<9, 512>>>(W2, b2,  2,  2, 0);   // T16  -> g_T[0]
    step_k<<<9, 512>>>(W2, b2,  0,  0, 1);   // T32  -> g_T[1]
    step_k<<<9, 512>>>(W2, b2,  1,  1, 3);   // T64  -> g_T[3]  (kept)
    step_k<<<9, 512>>>(W2, b2,  3,  3, 0);   // T128 -> g_T[0]
    step_k<<<9, 512>>>(W2, b2,  0,  3, 1);   // T192 -> g_T[1]
    step_k<<<9, 512>>>(W2, b2,  1,  2, 0);   // T200 -> g_T[0]
    fold_k<<<22, 512>>>(W1, b1);             // g_W1f from g_T[0]
    conv_k<<<128, 256, CONV_SMEM>>>(x, out);
}

// round 3
// speedup vs baseline: 1.2578x; 1.2578x over previous
#include <cuda_runtime.h>

typedef unsigned long long u64;

#define GRID_BLKS 129
#define NT 256
#define SMEM_FLOATS 33024   // chain block dominates: 8*4096 + 4*64

__device__ float g_AT[4096];
__device__ float g_sA[64];
__device__ int   g_flag = 0;
__device__ int   g_done = 0;

__device__ __forceinline__ u64 pk2(float a, float b) {
    u64 r; asm("mov.b64 %0, {%1, %2};" : "=l"(r) : "f"(a), "f"(b)); return r;
}
__device__ __forceinline__ float2 up2(u64 v) {
    float2 r; asm("mov.b64 {%0, %1}, %2;" : "=f"(r.x), "=f"(r.y) : "l"(v)); return r;
}
__device__ __forceinline__ void fma2(u64& d, u64 a, u64 b) {
    asm("fma.rn.f32x2 %0, %1, %2, %0;" : "+l"(d) : "l"(a), "l"(b));
}

// C = A*B affine compose on 64x64 (+ s vector). AT = A transposed [k][r],
// Brm = B natural [k][c]. Writes C in both layouts + Cs.
__device__ __forceinline__ void compose(const float* __restrict__ AT,
                                        const float* __restrict__ Brm,
                                        const float* __restrict__ As,
                                        const float* __restrict__ Bs,
                                        float* Crm, float* CT, float* Cs, int t)
{
    const int r0 = (t >> 4) << 2, c0 = (t & 15) << 2;
    u64 acc0[4] = {0, 0, 0, 0}, acc1[4] = {0, 0, 0, 0};
#pragma unroll 4
    for (int k = 0; k < 64; ++k) {
        float4 a = *(const float4*)(AT + k * 64 + r0);
        float4 b = *(const float4*)(Brm + k * 64 + c0);
        u64 a01 = pk2(a.x, a.y), a23 = pk2(a.z, a.w);
        u64 bb0 = pk2(b.x, b.x), bb1 = pk2(b.y, b.y);
        u64 bb2 = pk2(b.z, b.z), bb3 = pk2(b.w, b.w);
        fma2(acc0[0], a01, bb0); fma2(acc0[1], a01, bb1);
        fma2(acc0[2], a01, bb2); fma2(acc0[3], a01, bb3);
        fma2(acc1[0], a23, bb0); fma2(acc1[1], a23, bb1);
        fma2(acc1[2], a23, bb2); fma2(acc1[3], a23, bb3);
    }
    float2 p0 = up2(acc0[0]), p1 = up2(acc0[1]), p2 = up2(acc0[2]), p3 = up2(acc0[3]);
    float2 q0 = up2(acc1[0]), q1 = up2(acc1[1]), q2 = up2(acc1[2]), q3 = up2(acc1[3]);
    *(float4*)(Crm + (r0 + 0) * 64 + c0) = make_float4(p0.x, p1.x, p2.x, p3.x);
    *(float4*)(Crm + (r0 + 1) * 64 + c0) = make_float4(p0.y, p1.y, p2.y, p3.y);
    *(float4*)(Crm + (r0 + 2) * 64 + c0) = make_float4(q0.x, q1.x, q2.x, q3.x);
    *(float4*)(Crm + (r0 + 3) * 64 + c0) = make_float4(q0.y, q1.y, q2.y, q3.y);
    *(float4*)(CT + (c0 + 0) * 64 + r0) = make_float4(p0.x, p0.y, q0.x, q0.y);
    *(float4*)(CT + (c0 + 1) * 64 + r0) = make_float4(p1.x, p1.y, q1.x, q1.y);
    *(float4*)(CT + (c0 + 2) * 64 + r0) = make_float4(p2.x, p2.y, q2.x, q2.y);
    *(float4*)(CT + (c0 + 3) * 64 + r0) = make_float4(p3.x, p3.y, q3.x, q3.y);
    if (t < 64) {
        float s = As[t];
#pragma unroll 8
        for (int k = 0; k < 64; ++k)
            s = fmaf(AT[k * 64 + t], Bs[k], s);
        Cs[t] = s;
    }
}

__global__ void __launch_bounds__(NT, 1)
fused(const float* __restrict__ x, const float* __restrict__ W1,
      const float* __restrict__ b1, const float* __restrict__ W2,
      const float* __restrict__ b2, float* __restrict__ out)
{
    extern __shared__ float sm[];
    const int t   = threadIdx.x;
    const int bid = blockIdx.x;

    if (bid == 0) {
        // ================= chain block =================
        // buffers: 0 = W2/b2, 1 = T5, 2/3 = ping-pong
        float* rm[4]; float* Tm[4]; float* sv[4];
#pragma unroll
        for (int i = 0; i < 4; ++i) {
            rm[i] = sm + i * 4096;
            Tm[i] = sm + 16384 + i * 4096;
            sv[i] = sm + 32768 + i * 64;
        }
        for (int i = t; i < 4096; i += NT) {
            float v = W2[i];
            rm[0][i] = v;
            Tm[0][(i & 63) * 64 + (i >> 6)] = v;
        }
        if (t < 64) sv[0][t] = b2[t];
        __syncthreads();

        // addition chain: 2,4,5,10,20,25,50,100,200
        const int sa_[9] = {0, 2, 3, 1, 2, 3, 2, 3, 2};
        const int sb_[9] = {0, 2, 0, 1, 2, 1, 2, 3, 2};
        const int sc_[9] = {2, 3, 1, 2, 3, 2, 3, 2, 3};
#pragma unroll 1
        for (int s = 0; s < 9; ++s) {
            int a = sa_[s], b = sb_[s], c = sc_[s];
            compose(Tm[a], rm[b], sv[a], sv[b], rm[c], Tm[c], sv[c], t);
            __syncthreads();
        }
        // publish A^T = Tm[3], sA = sv[3]
        for (int i = t; i < 4096; i += NT) g_AT[i] = Tm[3][i];
        if (t < 64) g_sA[t] = sv[3][t];
        __threadfence();
        __syncthreads();
        if (t == 0) atomicExch(&g_flag, 1);
    } else {
        // ================= conv + apply block =================
        float* W1s = sm;             // 64 x 168
        float* xs  = sm + 10752;     // 2 x 3 x 7 x 72
        float* h0  = sm + 13776;     // 64 x 128  (channel x pixel)
        float* ATs = sm + 21968;     // 64 x 64
        float* sAs = sm + 26064;     // 64
        float* b1s = sm + 26128;     // 64

        const int r0 = (bid - 1) * 2;
        const int bb = r0 >> 6, y0 = r0 & 63;   // both rows in same image

        for (int i = t; i < 10752; i += NT) {
            int m = i / 168, jp = i % 168;
            int ii = jp / 56, r = jp % 56, ky = r / 8, kx = r % 8;
            W1s[i] = (kx < 7) ? W1[m * 147 + ii * 49 + ky * 7 + kx] : 0.0f;
        }
        if (t < 64) b1s[t] = b1[t];
        for (int i = t; i < 3024; i += NT) {
            int row = i / 1512, rem = i % 1512;
            int ii = rem / 504, rem2 = rem % 504;
            int ky = rem2 / 72, xx = rem2 % 72;
            int yy = y0 + row + ky;
            xs[i] = (xx < 70) ? x[((bb * 3 + ii) * 70 + yy) * 70 + xx] : 0.0f;
        }
        __syncthreads();

        // ---- conv h0 = conv7x7(x, W1) + b1, rows paired in f32x2 ----
        const int xq = t & 7, op = t >> 3;
        const int x0 = xq * 8, o0 = op * 2;

        u64 acc[2][8];
#pragma unroll
        for (int oo = 0; oo < 2; ++oo) {
            u64 bv = pk2(b1s[o0 + oo], b1s[o0 + oo]);
#pragma unroll
            for (int xi = 0; xi < 8; ++xi) acc[oo][xi] = bv;
        }

#pragma unroll 1
        for (int ii = 0; ii < 3; ++ii) {
#pragma unroll 1
            for (int ky = 0; ky < 7; ++ky) {
                const float* p0 = xs + (ii * 7 + ky) * 72 + x0;
                const float* p1 = p0 + 1512;
                float a0[16], a1[16];
#pragma unroll
                for (int q = 0; q < 4; ++q) {
                    float4 u = *(const float4*)(p0 + q * 4);
                    a0[q*4+0] = u.x; a0[q*4+1] = u.y; a0[q*4+2] = u.z; a0[q*4+3] = u.w;
                    float4 v = *(const float4*)(p1 + q * 4);
                    a1[q*4+0] = v.x; a1[q*4+1] = v.y; a1[q*4+2] = v.z; a1[q*4+3] = v.w;
                }
                u64 xwp[16];
#pragma unroll
                for (int i = 0; i < 16; ++i) xwp[i] = pk2(a0[i], a1[i]);

                u64 wp[2][7];
#pragma unroll
                for (int oo = 0; oo < 2; ++oo) {
                    const float* wq = W1s + (o0 + oo) * 168 + ii * 56 + ky * 8;
                    float4 w0 = *(const float4*)(wq);
                    float4 w1 = *(const float4*)(wq + 4);
                    wp[oo][0] = pk2(w0.x, w0.x); wp[oo][1] = pk2(w0.y, w0.y);
                    wp[oo][2] = pk2(w0.z, w0.z); wp[oo][3] = pk2(w0.w, w0.w);
                    wp[oo][4] = pk2(w1.x, w1.x); wp[oo][5] = pk2(w1.y, w1.y);
                    wp[oo][6] = pk2(w1.z, w1.z);
                }
#pragma unroll
                for (int kx = 0; kx < 7; ++kx)
#pragma unroll
                    for (int oo = 0; oo < 2; ++oo)
#pragma unroll
                        for (int xi = 0; xi < 8; ++xi)
                            fma2(acc[oo][xi], wp[oo][kx], xwp[kx + xi]);
            }
        }

        // ---- h0 -> smem [c][px], px = row*64 + x ----
#pragma unroll
        for (int oo = 0; oo < 2; ++oo) {
            int o = o0 + oo;
            float2 v[8];
#pragma unroll
            for (int xi = 0; xi < 8; ++xi) v[xi] = up2(acc[oo][xi]);
            *(float4*)(h0 + o * 128 + x0)          = make_float4(v[0].x, v[1].x, v[2].x, v[3].x);
            *(float4*)(h0 + o * 128 + x0 + 4)      = make_float4(v[4].x, v[5].x, v[6].x, v[7].x);
            *(float4*)(h0 + o * 128 + 64 + x0)     = make_float4(v[0].y, v[1].y, v[2].y, v[3].y);
            *(float4*)(h0 + o * 128 + 64 + x0 + 4) = make_float4(v[4].y, v[5].y, v[6].y, v[7].y);
        }
        __syncthreads();

        // ---- wait for chain ----
        if (t == 0) {
            while (atomicAdd(&g_flag, 0) == 0) __nanosleep(64);
            __threadfence();
        }
        __syncthreads();
        for (int i = t; i < 4096; i += NT) ATs[i] = __ldcg(&g_AT[i]);
        if (t < 64) sAs[t] = __ldcg(&g_sA[t]);
        __syncthreads();

        // ---- apply: out = A*h0 + sA ----
        const int po = t >> 4, pq = t & 15;
        const int oa = po * 4, px0 = pq * 8;

        u64 ap[4][4];
#pragma unroll
        for (int j = 0; j < 4; ++j)
#pragma unroll
            for (int p = 0; p < 4; ++p) ap[j][p] = 0ULL;

#pragma unroll 4
        for (int c = 0; c < 64; ++c) {
            float4 av  = *(const float4*)(ATs + c * 64 + oa);
            float4 h0v = *(const float4*)(h0 + c * 128 + px0);
            float4 h1v = *(const float4*)(h0 + c * 128 + px0 + 4);
            u64 aj0 = pk2(av.x, av.x), aj1 = pk2(av.y, av.y);
            u64 aj2 = pk2(av.z, av.z), aj3 = pk2(av.w, av.w);
            u64 hp0 = pk2(h0v.x, h0v.y), hp1 = pk2(h0v.z, h0v.w);
            u64 hp2 = pk2(h1v.x, h1v.y), hp3 = pk2(h1v.z, h1v.w);
            fma2(ap[0][0], aj0, hp0); fma2(ap[0][1], aj0, hp1);
            fma2(ap[0][2], aj0, hp2); fma2(ap[0][3], aj0, hp3);
            fma2(ap[1][0], aj1, hp0); fma2(ap[1][1], aj1, hp1);
            fma2(ap[1][2], aj1, hp2); fma2(ap[1][3], aj1, hp3);
            fma2(ap[2][0], aj2, hp0); fma2(ap[2][1], aj2, hp1);
            fma2(ap[2][2], aj2, hp2); fma2(ap[2][3], aj2, hp3);
            fma2(ap[3][0], aj3, hp0); fma2(ap[3][1], aj3, hp1);
            fma2(ap[3][2], aj3, hp2); fma2(ap[3][3], aj3, hp3);
        }

        const int rr  = px0 >> 6;       // row within the pair
        const int xx0 = px0 & 63;
        const int yy  = y0 + rr;
#pragma unroll
        for (int j = 0; j < 4; ++j) {
            int o = oa + j;
            float sa = sAs[o];
            float2 v0 = up2(ap[j][0]), v1 = up2(ap[j][1]);
            float2 v2 = up2(ap[j][2]), v3 = up2(ap[j][3]);
            float* pd = out + ((bb * 64 + o) * 64 + yy) * 64 + xx0;
            *(float4*)(pd)     = make_float4(v0.x + sa, v0.y + sa, v1.x + sa, v1.y + sa);
            *(float4*)(pd + 4) = make_float4(v2.x + sa, v2.y + sa, v3.x + sa, v3.y + sa);
        }
    }

    // ---- self-resetting flags so graph replays start clean ----
    __syncthreads();
    if (t == 0) {
        __threadfence();
        int d = atomicAdd(&g_done, 1);
        if (d == GRID_BLKS - 1) {
            atomicExch(&g_flag, 0);
            atomicExch(&g_done, 0);
        }
    }
}

extern "C" void kernel_launch(void* const* d_in, const int* in_sizes, int n_in,
                              void* d_out, int out_size)
{
    (void)in_sizes; (void)n_in; (void)out_size;
    const float* x  = (const float*)d_in[0];
    const float* W1 = (const float*)d_in[1];
    const float* b1 = (const float*)d_in[2];
    const float* W2 = (const float*)d_in[3];
    const float* b2 = (const float*)d_in[4];
    float* out = (float*)d_out;

    const size_t smem = (size_t)SMEM_FLOATS * sizeof(float);
    cudaFuncSetAttribute(fused, cudaFuncAttributeMaxDynamicSharedMemorySize, (int)smem);
    fused<<<GRID_BLKS, NT, smem>>>(x, W1, b1, W2, b2, out);
}